// round 7
// baseline (speedup 1.0000x reference)
#include <cuda_runtime.h>
#include <math.h>

// Fixed geometry: D=128, H=8, PAGE_SIZE=16, STREAMING_BUDGET=4096, NUM_SINK=4.
#define DD      128
#define HH      8
#define PAGE    16
#define BUDGET  4096
#define SINK    4
#define VEC_PER_ROW (DD/4)            // 32 float4 per head-row
#define F4_PER_PAGE (2*PAGE*HH*DD/4)  // 8192 float4 per page (k half then v half)

// log2(10000)/64, double precision
#define LOG2_1E4_OVER_64 0.20762050593045952

// ---- capture-fork plumbing: host-side objects only, created at load time ----
static cudaStream_t g_cs[2];
static cudaEvent_t  g_fork;
static cudaEvent_t  g_join[2];
struct SkvStreamInit {
    SkvStreamInit() {
        cudaEventCreateWithFlags(&g_fork, cudaEventDisableTiming);
        for (int i = 0; i < 2; i++) {
            cudaStreamCreateWithFlags(&g_cs[i], cudaStreamNonBlocking);
            cudaEventCreateWithFlags(&g_join[i], cudaEventDisableTiming);
        }
    }
};
static SkvStreamInit g_skv_stream_init;

// Source head-row pointer for the streaming-gather (kv = 0 keys / 1 values).
__device__ __forceinline__ const float4*
resolve_row(const float4* __restrict__ cache, const float4* __restrict__ fresh,
            int b, int p, int kv, int ctx, int ql, int maxkv, int seq_len)
{
    bool active  = (ql > 0);
    bool rolling = active && (ctx + ql >  BUDGET);
    bool plain   = active && (ctx + ql <= BUDGET);

    if (rolling && p >= SINK && p < BUDGET - ql) {
        int srs = min(ctx, BUDGET) - (BUDGET - ql - SINK);
        int pos = min(max(p + srs - SINK, 0), maxkv - 1);
        int gp  = b * maxkv + pos;
        return cache + (size_t)(gp >> 4) * F4_PER_PAGE
                     + (size_t)(kv * PAGE + (gp & 15)) * (HH * VEC_PER_ROW);
    }
    if ((rolling && p >= BUDGET - ql && p < BUDGET) ||
        (plain   && p >= ctx         && p < ctx + ql)) {
        int sp = rolling ? (p - (BUDGET - ql)) : (p - ctx);
        sp = min(max(sp, 0), seq_len - 1);
        return fresh + ((size_t)(b * seq_len + sp) * HH) * VEC_PER_ROW;
    }
    int gp = b * maxkv + p;
    return cache + (size_t)(gp >> 4) * F4_PER_PAGE
                 + (size_t)(kv * PAGE + (gp & 15)) * (HH * VEC_PER_ROW);
}

// Destination float4 base of head-row (b,p,kv) in the paged output.
__device__ __forceinline__ size_t out_row_base(int b, int p, int kv, int maxkv)
{
    int gp = b * maxkv + p;
    return (size_t)(gp >> 4) * F4_PER_PAGE
         + (size_t)(kv * PAGE + (gp & 15)) * (HH * VEC_PER_ROW);
}

// Fused kernel. Flat grid over three regions:
//   [0, nA)        rope'd keys, p<BUDGET. thread = float4 pair (d4, d4+16).
//   [nA, nAV)      value gather, p<BUDGET. thread = 2 consecutive float4.
//   [nAV, ntot)    identity copy, p>=BUDGET, batches [0, n_sm_batches) only.
//                  (Remaining batches' identity regions go via CE memcpys.)
__global__ __launch_bounds__(256)
void skv_fused(const float4* __restrict__ cache,
               const float4* __restrict__ knew,
               const float4* __restrict__ vnew,
               const int*    __restrict__ qlens,
               const int*    __restrict__ ctxp,
               float4*       __restrict__ out,
               int maxkv, int seq_len,
               int nA, int nAV,
               int id_shift, int id_mask, int ntot)
{
    __shared__ float sfreq[DD/2];
    int tid = threadIdx.x;
    int gid = blockIdx.x * 256 + tid;
    int blk0 = blockIdx.x * 256;

    // Blocks overlapping the rope region build the inv_freq table in smem
    // (double exp2 -> correctly-rounded fp32, same values as a double pow).
    if (blk0 < nA) {
        if (tid < DD/2)
            sfreq[tid] = (float)exp2(-(double)tid * LOG2_1E4_OVER_64);
        __syncthreads();
    }

    if (gid >= ntot) return;

    if (gid < nA) {
        // ---- RoPE keys ----
        int d4 = gid & 15;                 // lower-half float4 index (0..15)
        int h  = (gid >> 4) & (HH - 1);
        int p  = (gid >> 7) & (BUDGET - 1);
        int b  = gid >> 19;

        int ctx = *ctxp;
        int ql  = __ldg(&qlens[b]);

        const float4* row = resolve_row(cache, knew, b, p, 0, ctx, ql, maxkv, seq_len)
                            + h * VEC_PER_ROW;
        float4 x1 = __ldg(&row[d4]);
        float4 x2 = __ldg(&row[d4 + 16]);

        float fp = (float)p;
        int i0 = d4 * 4;
        float4 lo, hi;
        const float* a  = (const float*)&x1;
        const float* bb = (const float*)&x2;
        float* lf = (float*)&lo;
        float* hf = (float*)&hi;
        #pragma unroll
        for (int j = 0; j < 4; j++) {
            float s, c;
            sincosf(fp * sfreq[i0 + j], &s, &c);
            lf[j] = a[j] * c - bb[j] * s;
            hf[j] = a[j] * s + bb[j] * c;
        }

        float4* orow = out + out_row_base(b, p, 0, maxkv) + h * VEC_PER_ROW;
        orow[d4]      = lo;
        orow[d4 + 16] = hi;
    } else if (gid < nAV) {
        // ---- value gather, p < BUDGET ----
        int j  = gid - nA;
        int d4 = (j & 15) * 2;             // pair of consecutive float4
        int h  = (j >> 4) & (HH - 1);
        int p  = (j >> 7) & (BUDGET - 1);
        int b  = j >> 19;

        int ctx = *ctxp;
        int ql  = __ldg(&qlens[b]);
        const float4* row = resolve_row(cache, vnew, b, p, 1, ctx, ql, maxkv, seq_len)
                            + h * VEC_PER_ROW;
        float4 v0 = __ldg(&row[d4]);
        float4 v1 = __ldg(&row[d4 + 1]);
        float4* orow = out + out_row_base(b, p, 1, maxkv) + h * VEC_PER_ROW;
        orow[d4]     = v0;
        orow[d4 + 1] = v1;
    } else {
        // ---- identity region (SM share): batch = j>>id_shift, in [0,n_sm) ----
        int j = gid - nAV;
        int b = j >> id_shift;
        long long off = (long long)(j & id_mask);   // f4-pair offset in chunk
        long long base = ((long long)b * (maxkv / PAGE) + (BUDGET / PAGE))
                         * F4_PER_PAGE;
        long long idx = base + off * 2;
        float4 v0 = __ldg(&cache[idx]);
        float4 v1 = __ldg(&cache[idx + 1]);
        out[idx]     = v0;
        out[idx + 1] = v1;
    }
}

extern "C" void kernel_launch(void* const* d_in, const int* in_sizes, int n_in,
                              void* d_out, int out_size) {
    const float4* cache = (const float4*)d_in[0];
    const float4* knew  = (const float4*)d_in[1];
    const float4* vnew  = (const float4*)d_in[2];
    const int*    qlens = (const int*)d_in[3];
    const int*    ctxp  = (const int*)d_in[5];   // context_len scalar (device)
    float4*       out   = (float4*)d_out;

    int bsz = in_sizes[3];
    int total_pos = in_sizes[0] / (2 * HH * DD);
    int maxkv = total_pos / bsz;                 // 8192
    int seq_len = in_sizes[1] / (bsz * HH * DD); // 2048

    // Region sizes (threads)
    int nA  = bsz * BUDGET * HH * (VEC_PER_ROW / 2);   // rope pairs
    int nV  = bsz * BUDGET * HH * (VEC_PER_ROW / 2);   // value 32B units
    int nAV = nA + nV;

    int id_pages = maxkv / PAGE - BUDGET / PAGE;                 // per batch
    long long id_pairs = (long long)id_pages * F4_PER_PAGE / 2;  // per batch (pow2)
    int id_shift = 0;
    while ((1LL << id_shift) < id_pairs) id_shift++;
    int id_mask = (int)(id_pairs - 1);

    // Last n_ce batches' identity regions go via copy engines.
    int n_ce = bsz / 2;
    if (n_ce > 2) n_ce = 2;
    int n_sm_batches = bsz - n_ce;

    int ntot = nAV + (int)(id_pairs * n_sm_batches);
    int blocks = (ntot + 255) / 256;

    // Fork: CE copies run concurrently with the SM kernel inside the graph.
    cudaEventRecord(g_fork, 0);
    size_t id_bytes = (size_t)id_pages * F4_PER_PAGE * sizeof(float4);
    for (int i = 0; i < n_ce; i++) {
        int b = n_sm_batches + i;
        size_t f4_base = ((size_t)b * (maxkv / PAGE) + (BUDGET / PAGE))
                         * F4_PER_PAGE;
        cudaStreamWaitEvent(g_cs[i], g_fork, 0);
        cudaMemcpyAsync(out + f4_base, cache + f4_base, id_bytes,
                        cudaMemcpyDeviceToDevice, g_cs[i]);
        cudaEventRecord(g_join[i], g_cs[i]);
    }

    skv_fused<<<blocks, 256>>>(cache, knew, vnew, qlens, ctxp,
                               out, maxkv, seq_len,
                               nA, nAV, id_shift, id_mask, ntot);

    for (int i = 0; i < n_ce; i++)
        cudaStreamWaitEvent(0, g_join[i], 0);
}

// round 8
// speedup vs baseline: 1.0098x; 1.0098x over previous
#include <cuda_runtime.h>
#include <math.h>

// Fixed geometry: D=128, H=8, PAGE_SIZE=16, STREAMING_BUDGET=4096, NUM_SINK=4.
#define DD      128
#define HH      8
#define PAGE    16
#define BUDGET  4096
#define SINK    4
#define VEC_PER_ROW (DD/4)            // 32 float4 per head-row
#define F4_PER_PAGE (2*PAGE*HH*DD/4)  // 8192 float4 per page (k half then v half)

// log2(10000)/64, double precision
#define LOG2_1E4_OVER_64 0.20762050593045952

// Source head-row pointer for the streaming-gather (kv = 0 keys / 1 values).
__device__ __forceinline__ const float4*
resolve_row(const float4* __restrict__ cache, const float4* __restrict__ fresh,
            int b, int p, int kv, int ctx, int ql, int maxkv, int seq_len)
{
    bool active  = (ql > 0);
    bool rolling = active && (ctx + ql >  BUDGET);
    bool plain   = active && (ctx + ql <= BUDGET);

    if (rolling && p >= SINK && p < BUDGET - ql) {
        int srs = min(ctx, BUDGET) - (BUDGET - ql - SINK);
        int pos = min(max(p + srs - SINK, 0), maxkv - 1);
        int gp  = b * maxkv + pos;
        return cache + (size_t)(gp >> 4) * F4_PER_PAGE
                     + (size_t)(kv * PAGE + (gp & 15)) * (HH * VEC_PER_ROW);
    }
    if ((rolling && p >= BUDGET - ql && p < BUDGET) ||
        (plain   && p >= ctx         && p < ctx + ql)) {
        int sp = rolling ? (p - (BUDGET - ql)) : (p - ctx);
        sp = min(max(sp, 0), seq_len - 1);
        return fresh + ((size_t)(b * seq_len + sp) * HH) * VEC_PER_ROW;
    }
    int gp = b * maxkv + p;
    return cache + (size_t)(gp >> 4) * F4_PER_PAGE
                 + (size_t)(kv * PAGE + (gp & 15)) * (HH * VEC_PER_ROW);
}

// Destination float4 base of head-row (b,p,kv) in the paged output.
__device__ __forceinline__ size_t out_row_base(int b, int p, int kv, int maxkv)
{
    int gp = b * maxkv + p;
    return (size_t)(gp >> 4) * F4_PER_PAGE
         + (size_t)(kv * PAGE + (gp & 15)) * (HH * VEC_PER_ROW);
}

// Value-gather unit (32B): decode j -> source/dest addresses.
__device__ __forceinline__ void
vunit_addrs(int j, const float4* __restrict__ cache, const float4* __restrict__ vnew,
            const int* __restrict__ qlens, int ctx, int maxkv, int seq_len,
            float4* __restrict__ out,
            const float4** src, float4** dst, int* d4o)
{
    int d4 = (j & 15) * 2;
    int h  = (j >> 4) & (HH - 1);
    int p  = (j >> 7) & (BUDGET - 1);
    int b  = j >> 19;
    int ql = __ldg(&qlens[b]);
    *src = resolve_row(cache, vnew, b, p, 1, ctx, ql, maxkv, seq_len)
           + h * VEC_PER_ROW;
    *dst = out + out_row_base(b, p, 1, maxkv) + h * VEC_PER_ROW;
    *d4o = d4;
}

// Fused kernel. Flat grid over three regions:
//   [0, nA)          rope'd keys, p<BUDGET. thread = float4 pair (d4, d4+16).
//   [nA, nA+nVh)     value gather: thread = 2 interleaved 32B units (j, j+nVh).
//   [nA+nVh, ntot)   identity copy: thread = 2 interleaved 32B units (u, u+nIh).
__global__ __launch_bounds__(256)
void skv_fused(const float4* __restrict__ cache,
               const float4* __restrict__ knew,
               const float4* __restrict__ vnew,
               const int*    __restrict__ qlens,
               const int*    __restrict__ ctxp,
               float4*       __restrict__ out,
               int maxkv, int seq_len,
               int nA, int nVh, int nIh,
               int id_shift, int id_mask, int ntot)
{
    __shared__ float sfreq[DD/2];
    int tid = threadIdx.x;
    int gid = blockIdx.x * 256 + tid;
    int blk0 = blockIdx.x * 256;

    // Blocks overlapping the rope region build the inv_freq table in smem
    // (double exp2 -> correctly-rounded fp32, same values as a double pow).
    if (blk0 < nA) {
        if (tid < DD/2)
            sfreq[tid] = (float)exp2(-(double)tid * LOG2_1E4_OVER_64);
        __syncthreads();
    }

    if (gid >= ntot) return;

    if (gid < nA) {
        // ---- RoPE keys (unchanged from R4) ----
        int d4 = gid & 15;
        int h  = (gid >> 4) & (HH - 1);
        int p  = (gid >> 7) & (BUDGET - 1);
        int b  = gid >> 19;

        int ctx = *ctxp;
        int ql  = __ldg(&qlens[b]);

        const float4* row = resolve_row(cache, knew, b, p, 0, ctx, ql, maxkv, seq_len)
                            + h * VEC_PER_ROW;
        float4 x1 = __ldg(&row[d4]);
        float4 x2 = __ldg(&row[d4 + 16]);

        float fp = (float)p;
        int i0 = d4 * 4;
        float4 lo, hi;
        const float* a  = (const float*)&x1;
        const float* bb = (const float*)&x2;
        float* lf = (float*)&lo;
        float* hf = (float*)&hi;
        #pragma unroll
        for (int j = 0; j < 4; j++) {
            float s, c;
            sincosf(fp * sfreq[i0 + j], &s, &c);
            lf[j] = a[j] * c - bb[j] * s;
            hf[j] = a[j] * s + bb[j] * c;
        }

        float4* orow = out + out_row_base(b, p, 0, maxkv) + h * VEC_PER_ROW;
        orow[d4]      = lo;
        orow[d4 + 16] = hi;
    } else if (gid < nA + nVh) {
        // ---- value gather: 2 interleaved 32B units -> MLP 4, coalesced ----
        int j0 = gid - nA;
        int j1 = j0 + nVh;
        int ctx = *ctxp;

        const float4 *sA, *sB;
        float4 *dA, *dB;
        int dA4, dB4;
        vunit_addrs(j0, cache, vnew, qlens, ctx, maxkv, seq_len, out, &sA, &dA, &dA4);
        vunit_addrs(j1, cache, vnew, qlens, ctx, maxkv, seq_len, out, &sB, &dB, &dB4);

        float4 a0 = __ldg(&sA[dA4]);
        float4 a1 = __ldg(&sA[dA4 + 1]);
        float4 b0 = __ldg(&sB[dB4]);
        float4 b1 = __ldg(&sB[dB4 + 1]);
        dA[dA4]     = a0;
        dA[dA4 + 1] = a1;
        dB[dB4]     = b0;
        dB[dB4 + 1] = b1;
    } else {
        // ---- identity: 2 interleaved 32B units -> MLP 4, coalesced ----
        int u0 = gid - nA - nVh;
        int u1 = u0 + nIh;

        int bA = u0 >> id_shift;
        int bB = u1 >> id_shift;
        long long offA = (long long)(u0 & id_mask);
        long long offB = (long long)(u1 & id_mask);
        long long baseA = ((long long)bA * (maxkv / PAGE) + (BUDGET / PAGE))
                          * F4_PER_PAGE;
        long long baseB = ((long long)bB * (maxkv / PAGE) + (BUDGET / PAGE))
                          * F4_PER_PAGE;
        long long idxA = baseA + offA * 2;
        long long idxB = baseB + offB * 2;

        float4 a0 = __ldg(&cache[idxA]);
        float4 a1 = __ldg(&cache[idxA + 1]);
        float4 b0 = __ldg(&cache[idxB]);
        float4 b1 = __ldg(&cache[idxB + 1]);
        out[idxA]     = a0;
        out[idxA + 1] = a1;
        out[idxB]     = b0;
        out[idxB + 1] = b1;
    }
}

extern "C" void kernel_launch(void* const* d_in, const int* in_sizes, int n_in,
                              void* d_out, int out_size) {
    const float4* cache = (const float4*)d_in[0];
    const float4* knew  = (const float4*)d_in[1];
    const float4* vnew  = (const float4*)d_in[2];
    const int*    qlens = (const int*)d_in[3];
    const int*    ctxp  = (const int*)d_in[5];   // context_len scalar (device)

    int bsz = in_sizes[3];
    int total_pos = in_sizes[0] / (2 * HH * DD);
    int maxkv = total_pos / bsz;                 // 8192
    int seq_len = in_sizes[1] / (bsz * HH * DD); // 2048

    // Region sizes
    int nA  = bsz * BUDGET * HH * (VEC_PER_ROW / 2);   // rope pairs (threads)
    int nV  = bsz * BUDGET * HH * (VEC_PER_ROW / 2);   // value 32B units
    int nVh = nV / 2;                                  // threads (2 units each)

    int id_pages = maxkv / PAGE - BUDGET / PAGE;                 // per batch
    long long id_pairs = (long long)id_pages * F4_PER_PAGE / 2;  // 32B units/batch (pow2)
    int id_shift = 0;
    while ((1LL << id_shift) < id_pairs) id_shift++;
    int id_mask = (int)(id_pairs - 1);
    int nId = (int)(id_pairs * bsz);                   // total identity 32B units
    int nIh = nId / 2;                                 // threads (2 units each)

    int ntot = nA + nVh + nIh;
    int blocks = (ntot + 255) / 256;

    skv_fused<<<blocks, 256>>>(cache, knew, vnew, qlens, ctxp,
                               (float4*)d_out, maxkv, seq_len,
                               nA, nVh, nIh, id_shift, id_mask, ntot);
}

// round 9
// speedup vs baseline: 1.0131x; 1.0033x over previous
#include <cuda_runtime.h>
#include <math.h>

// Fixed geometry: D=128, H=8, PAGE_SIZE=16, STREAMING_BUDGET=4096, NUM_SINK=4.
#define DD      128
#define HH      8
#define PAGE    16
#define BUDGET  4096
#define SINK    4
#define VEC_PER_ROW (DD/4)            // 32 float4 per head-row
#define F4_PER_PAGE (2*PAGE*HH*DD/4)  // 8192 float4 per page (k half then v half)

// log2(10000)/64, double precision
#define LOG2_1E4_OVER_64 0.20762050593045952

// Source head-row pointer for the streaming-gather (kv = 0 keys / 1 values).
__device__ __forceinline__ const float4*
resolve_row(const float4* __restrict__ cache, const float4* __restrict__ fresh,
            int b, int p, int kv, int ctx, int ql, int maxkv, int seq_len)
{
    bool active  = (ql > 0);
    bool rolling = active && (ctx + ql >  BUDGET);
    bool plain   = active && (ctx + ql <= BUDGET);

    if (rolling && p >= SINK && p < BUDGET - ql) {
        int srs = min(ctx, BUDGET) - (BUDGET - ql - SINK);
        int pos = min(max(p + srs - SINK, 0), maxkv - 1);
        int gp  = b * maxkv + pos;
        return cache + (size_t)(gp >> 4) * F4_PER_PAGE
                     + (size_t)(kv * PAGE + (gp & 15)) * (HH * VEC_PER_ROW);
    }
    if ((rolling && p >= BUDGET - ql && p < BUDGET) ||
        (plain   && p >= ctx         && p < ctx + ql)) {
        int sp = rolling ? (p - (BUDGET - ql)) : (p - ctx);
        sp = min(max(sp, 0), seq_len - 1);
        return fresh + ((size_t)(b * seq_len + sp) * HH) * VEC_PER_ROW;
    }
    int gp = b * maxkv + p;
    return cache + (size_t)(gp >> 4) * F4_PER_PAGE
                 + (size_t)(kv * PAGE + (gp & 15)) * (HH * VEC_PER_ROW);
}

// Destination float4 base of position (b,p,kv) in the paged output (head 0).
__device__ __forceinline__ size_t out_row_base(int b, int p, int kv, int maxkv)
{
    int gp = b * maxkv + p;
    return (size_t)(gp >> 4) * F4_PER_PAGE
         + (size_t)(kv * PAGE + (gp & 15)) * (HH * VEC_PER_ROW);
}

// Fused kernel. Flat grid over three regions (thread counts identical to R4):
//   [0, nA)        rope'd keys, p<BUDGET. thread = float4 pair (d4, d4+16).
//   [nA, nAV)      value gather: thread = f4 `lane` of heads (2m, 2m+1)
//                  -> both LDG/STG warp-contiguous (512B runs).
//   [nAV, ntot)    identity copy: thread = f4 (w, w+32) of a 64-f4 group
//                  -> both LDG/STG warp-contiguous.
__global__ __launch_bounds__(256)
void skv_fused(const float4* __restrict__ cache,
               const float4* __restrict__ knew,
               const float4* __restrict__ vnew,
               const int*    __restrict__ qlens,
               const int*    __restrict__ ctxp,
               float4*       __restrict__ out,
               int maxkv, int seq_len,
               int nA, int nAV,
               int id_shift, int id_mask, int ntot)
{
    __shared__ float sfreq[DD/2];
    int tid = threadIdx.x;
    int gid = blockIdx.x * 256 + tid;
    int blk0 = blockIdx.x * 256;

    // Blocks overlapping the rope region build the inv_freq table in smem
    // (double exp2 -> correctly-rounded fp32, same values as a double pow).
    if (blk0 < nA) {
        if (tid < DD/2)
            sfreq[tid] = (float)exp2(-(double)tid * LOG2_1E4_OVER_64);
        __syncthreads();
    }

    if (gid >= ntot) return;

    if (gid < nA) {
        // ---- RoPE keys (unchanged from R4) ----
        int d4 = gid & 15;                 // lower-half float4 index (0..15)
        int h  = (gid >> 4) & (HH - 1);
        int p  = (gid >> 7) & (BUDGET - 1);
        int b  = gid >> 19;

        int ctx = *ctxp;
        int ql  = __ldg(&qlens[b]);

        const float4* row = resolve_row(cache, knew, b, p, 0, ctx, ql, maxkv, seq_len)
                            + h * VEC_PER_ROW;
        float4 x1 = __ldg(&row[d4]);
        float4 x2 = __ldg(&row[d4 + 16]);

        float fp = (float)p;
        int i0 = d4 * 4;
        float4 lo, hi;
        const float* a  = (const float*)&x1;
        const float* bb = (const float*)&x2;
        float* lf = (float*)&lo;
        float* hf = (float*)&hi;
        #pragma unroll
        for (int j = 0; j < 4; j++) {
            float s, c;
            sincosf(fp * sfreq[i0 + j], &s, &c);
            lf[j] = a[j] * c - bb[j] * s;
            hf[j] = a[j] * s + bb[j] * c;
        }

        float4* orow = out + out_row_base(b, p, 0, maxkv) + h * VEC_PER_ROW;
        orow[d4]      = lo;
        orow[d4 + 16] = hi;
    } else if (gid < nAV) {
        // ---- value gather: f4 `d4` of heads 2*hp and 2*hp+1 ----
        int j  = gid - nA;
        int d4 = j & 31;                   // f4 within head row (warp-contiguous)
        int hp = (j >> 5) & 3;             // head pair 0..3
        int p  = (j >> 7) & (BUDGET - 1);
        int b  = j >> 19;

        int ctx = *ctxp;
        int ql  = __ldg(&qlens[b]);
        // row base at head 2*hp; second head row is +VEC_PER_ROW (contiguous).
        const float4* row = resolve_row(cache, vnew, b, p, 1, ctx, ql, maxkv, seq_len)
                            + (hp * 2) * VEC_PER_ROW;
        float4 v0 = __ldg(&row[d4]);                    // head 2*hp
        float4 v1 = __ldg(&row[d4 + VEC_PER_ROW]);      // head 2*hp+1
        float4* orow = out + out_row_base(b, p, 1, maxkv) + (hp * 2) * VEC_PER_ROW;
        orow[d4]               = v0;
        orow[d4 + VEC_PER_ROW] = v1;
    } else {
        // ---- identity region: f4 (w, w+32) of a 64-f4 group ----
        int j = gid - nAV;
        int b = j >> id_shift;
        int w = j & id_mask;               // per-batch thread index
        long long base = ((long long)b * (maxkv / PAGE) + (BUDGET / PAGE))
                         * F4_PER_PAGE;
        long long idx = base + (long long)(w & ~31) * 2 + (w & 31);
        float4 v0 = __ldg(&cache[idx]);
        float4 v1 = __ldg(&cache[idx + 32]);
        out[idx]      = v0;
        out[idx + 32] = v1;
    }
}

extern "C" void kernel_launch(void* const* d_in, const int* in_sizes, int n_in,
                              void* d_out, int out_size) {
    const float4* cache = (const float4*)d_in[0];
    const float4* knew  = (const float4*)d_in[1];
    const float4* vnew  = (const float4*)d_in[2];
    const int*    qlens = (const int*)d_in[3];
    const int*    ctxp  = (const int*)d_in[5];   // context_len scalar (device)

    int bsz = in_sizes[3];
    int total_pos = in_sizes[0] / (2 * HH * DD);
    int maxkv = total_pos / bsz;                 // 8192
    int seq_len = in_sizes[1] / (bsz * HH * DD); // 2048

    // Region sizes (threads) — identical counts to R4.
    int nA  = bsz * BUDGET * HH * (VEC_PER_ROW / 2);   // rope pairs
    int nV  = bsz * BUDGET * HH * (VEC_PER_ROW / 2);   // value threads (2 f4 each)
    int nAV = nA + nV;

    int id_pages = maxkv / PAGE - BUDGET / PAGE;                   // per batch
    long long id_thr = (long long)id_pages * F4_PER_PAGE / 2;      // threads/batch (pow2)
    int id_shift = 0;
    while ((1LL << id_shift) < id_thr) id_shift++;
    int id_mask = (int)(id_thr - 1);

    int ntot = nAV + (int)(id_thr * bsz);
    int blocks = (ntot + 255) / 256;

    skv_fused<<<blocks, 256>>>(cache, knew, vnew, qlens, ctxp,
                               (float4*)d_out, maxkv, seq_len,
                               nA, nAV, id_shift, id_mask, ntot);
}

// round 10
// speedup vs baseline: 1.0349x; 1.0216x over previous
#include <cuda_runtime.h>
#include <math.h>

// Fixed geometry: D=128, H=8, PAGE_SIZE=16, STREAMING_BUDGET=4096, NUM_SINK=4.
#define DD      128
#define HH      8
#define PAGE    16
#define BUDGET  4096
#define SINK    4
#define VEC_PER_ROW (DD/4)            // 32 float4 per head-row
#define F4_PER_PAGE (2*PAGE*HH*DD/4)  // 8192 float4 per page (k half then v half)

// log2(10000)/64, double precision
#define LOG2_1E4_OVER_64 0.20762050593045952

// Source head-row pointer for the streaming-gather (kv = 0 keys / 1 values).
__device__ __forceinline__ const float4*
resolve_row(const float4* __restrict__ cache, const float4* __restrict__ fresh,
            int b, int p, int kv, int ctx, int ql, int maxkv, int seq_len)
{
    bool active  = (ql > 0);
    bool rolling = active && (ctx + ql >  BUDGET);
    bool plain   = active && (ctx + ql <= BUDGET);

    if (rolling && p >= SINK && p < BUDGET - ql) {
        int srs = min(ctx, BUDGET) - (BUDGET - ql - SINK);
        int pos = min(max(p + srs - SINK, 0), maxkv - 1);
        int gp  = b * maxkv + pos;
        return cache + (size_t)(gp >> 4) * F4_PER_PAGE
                     + (size_t)(kv * PAGE + (gp & 15)) * (HH * VEC_PER_ROW);
    }
    if ((rolling && p >= BUDGET - ql && p < BUDGET) ||
        (plain   && p >= ctx         && p < ctx + ql)) {
        int sp = rolling ? (p - (BUDGET - ql)) : (p - ctx);
        sp = min(max(sp, 0), seq_len - 1);
        return fresh + ((size_t)(b * seq_len + sp) * HH) * VEC_PER_ROW;
    }
    int gp = b * maxkv + p;
    return cache + (size_t)(gp >> 4) * F4_PER_PAGE
                 + (size_t)(kv * PAGE + (gp & 15)) * (HH * VEC_PER_ROW);
}

// Destination float4 base of head-row (b,p,kv) in the paged output.
__device__ __forceinline__ size_t out_row_base(int b, int p, int kv, int maxkv)
{
    int gp = b * maxkv + p;
    return (size_t)(gp >> 4) * F4_PER_PAGE
         + (size_t)(kv * PAGE + (gp & 15)) * (HH * VEC_PER_ROW);
}

// Fused single-launch kernel. Flat grid over three regions:
//   [0, nA)        rope'd keys, p<BUDGET. thread = float4 pair (d4, d4+16).
//   [nA, nAV)      value gather, p<BUDGET. thread = 2 consecutive float4.
//   [nAV, ntot)    identity copy, p>=BUDGET (masks all false). 2 float4/thread.
__global__ __launch_bounds__(256)
void skv_fused(const float4* __restrict__ cache,
               const float4* __restrict__ knew,
               const float4* __restrict__ vnew,
               const int*    __restrict__ qlens,
               const int*    __restrict__ ctxp,
               float4*       __restrict__ out,
               int maxkv, int seq_len,
               int nA, int nAV,
               int id_shift, int id_mask, int ntot)
{
    __shared__ float sfreq[DD/2];
    int tid = threadIdx.x;
    int gid = blockIdx.x * 256 + tid;
    int blk0 = blockIdx.x * 256;

    // Blocks overlapping the rope region build the inv_freq table in smem
    // (double exp2 -> correctly-rounded fp32, same values as a double pow).
    if (blk0 < nA) {
        if (tid < DD/2)
            sfreq[tid] = (float)exp2(-(double)tid * LOG2_1E4_OVER_64);
        __syncthreads();
    }

    if (gid >= ntot) return;

    if (gid < nA) {
        // ---- RoPE keys ----
        int d4 = gid & 15;                 // lower-half float4 index (0..15)
        int h  = (gid >> 4) & (HH - 1);
        int p  = (gid >> 7) & (BUDGET - 1);
        int b  = gid >> 19;

        int ctx = *ctxp;
        int ql  = __ldg(&qlens[b]);

        const float4* row = resolve_row(cache, knew, b, p, 0, ctx, ql, maxkv, seq_len)
                            + h * VEC_PER_ROW;
        float4 x1 = __ldg(&row[d4]);
        float4 x2 = __ldg(&row[d4 + 16]);

        float fp = (float)p;
        int i0 = d4 * 4;
        float4 lo, hi;
        const float* a  = (const float*)&x1;
        const float* bb = (const float*)&x2;
        float* lf = (float*)&lo;
        float* hf = (float*)&hi;
        #pragma unroll
        for (int j = 0; j < 4; j++) {
            float s, c;
            __sincosf(fp * sfreq[i0 + j], &s, &c);   // MUFU fast path
            lf[j] = a[j] * c - bb[j] * s;
            hf[j] = a[j] * s + bb[j] * c;
        }

        float4* orow = out + out_row_base(b, p, 0, maxkv) + h * VEC_PER_ROW;
        orow[d4]      = lo;
        orow[d4 + 16] = hi;
    } else if (gid < nAV) {
        // ---- value gather, p < BUDGET ----
        int j  = gid - nA;
        int d4 = (j & 15) * 2;             // pair of consecutive float4
        int h  = (j >> 4) & (HH - 1);
        int p  = (j >> 7) & (BUDGET - 1);
        int b  = j >> 19;

        int ctx = *ctxp;
        int ql  = __ldg(&qlens[b]);
        const float4* row = resolve_row(cache, vnew, b, p, 1, ctx, ql, maxkv, seq_len)
                            + h * VEC_PER_ROW;
        float4 v0 = __ldg(&row[d4]);
        float4 v1 = __ldg(&row[d4 + 1]);
        float4* orow = out + out_row_base(b, p, 1, maxkv) + h * VEC_PER_ROW;
        orow[d4]     = v0;
        orow[d4 + 1] = v1;
    } else {
        // ---- identity region: per batch, pages [BUDGET/16, maxkv/16) ----
        int j = gid - nAV;
        int b = j >> id_shift;
        long long off = (long long)(j & id_mask);   // f4-pair offset in chunk
        long long base = ((long long)b * (maxkv / PAGE) + (BUDGET / PAGE))
                         * F4_PER_PAGE;
        long long idx = base + off * 2;
        float4 v0 = __ldg(&cache[idx]);
        float4 v1 = __ldg(&cache[idx + 1]);
        out[idx]     = v0;
        out[idx + 1] = v1;
    }
}

extern "C" void kernel_launch(void* const* d_in, const int* in_sizes, int n_in,
                              void* d_out, int out_size) {
    const float4* cache = (const float4*)d_in[0];
    const float4* knew  = (const float4*)d_in[1];
    const float4* vnew  = (const float4*)d_in[2];
    const int*    qlens = (const int*)d_in[3];
    const int*    ctxp  = (const int*)d_in[5];   // context_len scalar (device)

    int bsz = in_sizes[3];
    int total_pos = in_sizes[0] / (2 * HH * DD);
    int maxkv = total_pos / bsz;                 // 8192
    int seq_len = in_sizes[1] / (bsz * HH * DD); // 2048

    // Region sizes (threads)
    int nA  = bsz * BUDGET * HH * (VEC_PER_ROW / 2);   // rope pairs
    int nV  = bsz * BUDGET * HH * (VEC_PER_ROW / 2);   // value 32B units
    int nAV = nA + nV;

    int id_pages = maxkv / PAGE - BUDGET / PAGE;                 // per batch
    long long id_pairs = (long long)id_pages * F4_PER_PAGE / 2;  // per batch (pow2)
    int id_shift = 0;
    while ((1LL << id_shift) < id_pairs) id_shift++;
    int id_mask = (int)(id_pairs - 1);

    int ntot = nAV + (int)(id_pairs * bsz);
    int blocks = (ntot + 255) / 256;

    skv_fused<<<blocks, 256>>>(cache, knew, vnew, qlens, ctxp,
                               (float4*)d_out, maxkv, seq_len,
                               nA, nAV, id_shift, id_mask, ntot);
}

// round 11
// speedup vs baseline: 1.0353x; 1.0004x over previous
#include <cuda_runtime.h>
#include <math.h>

// Fixed geometry: D=128, H=8, PAGE_SIZE=16, STREAMING_BUDGET=4096, NUM_SINK=4.
#define DD      128
#define HH      8
#define PAGE    16
#define BUDGET  4096
#define SINK    4
#define VEC_PER_ROW (DD/4)            // 32 float4 per head-row
#define F4_PER_PAGE (2*PAGE*HH*DD/4)  // 8192 float4 per page (k half then v half)

// log2(10000)/64, double precision
#define LOG2_1E4_OVER_64 0.20762050593045952

// Source head-row pointer for the streaming-gather (kv = 0 keys / 1 values).
__device__ __forceinline__ const float4*
resolve_row(const float4* __restrict__ cache, const float4* __restrict__ fresh,
            int b, int p, int kv, int ctx, int ql, int maxkv, int seq_len)
{
    bool active  = (ql > 0);
    bool rolling = active && (ctx + ql >  BUDGET);
    bool plain   = active && (ctx + ql <= BUDGET);

    if (rolling && p >= SINK && p < BUDGET - ql) {
        int srs = min(ctx, BUDGET) - (BUDGET - ql - SINK);
        int pos = min(max(p + srs - SINK, 0), maxkv - 1);
        int gp  = b * maxkv + pos;
        return cache + (size_t)(gp >> 4) * F4_PER_PAGE
                     + (size_t)(kv * PAGE + (gp & 15)) * (HH * VEC_PER_ROW);
    }
    if ((rolling && p >= BUDGET - ql && p < BUDGET) ||
        (plain   && p >= ctx         && p < ctx + ql)) {
        int sp = rolling ? (p - (BUDGET - ql)) : (p - ctx);
        sp = min(max(sp, 0), seq_len - 1);
        return fresh + ((size_t)(b * seq_len + sp) * HH) * VEC_PER_ROW;
    }
    int gp = b * maxkv + p;
    return cache + (size_t)(gp >> 4) * F4_PER_PAGE
                 + (size_t)(kv * PAGE + (gp & 15)) * (HH * VEC_PER_ROW);
}

// Destination float4 base of head-row (b,p,kv) in the paged output.
__device__ __forceinline__ size_t out_row_base(int b, int p, int kv, int maxkv)
{
    int gp = b * maxkv + p;
    return (size_t)(gp >> 4) * F4_PER_PAGE
         + (size_t)(kv * PAGE + (gp & 15)) * (HH * VEC_PER_ROW);
}

// Fused single-launch kernel. Flat grid over three regions:
//   [0, nA)        rope'd keys, p<BUDGET. thread = float4 pair (d4, d4+16).
//   [nA, nAV)      value gather, p<BUDGET. thread = 2 consecutive float4.
//   [nAV, ntot)    identity copy, p>=BUDGET: thread = 4 float4 at strides
//                  {0,32,64,96} in a 128-f4 group -> warp-contiguous, MLP 4.
__global__ __launch_bounds__(256)
void skv_fused(const float4* __restrict__ cache,
               const float4* __restrict__ knew,
               const float4* __restrict__ vnew,
               const int*    __restrict__ qlens,
               const int*    __restrict__ ctxp,
               float4*       __restrict__ out,
               int maxkv, int seq_len,
               int nA, int nAV,
               int id_shift, int id_mask, int ntot)
{
    __shared__ float sfreq[DD/2];
    int tid = threadIdx.x;
    int gid = blockIdx.x * 256 + tid;
    int blk0 = blockIdx.x * 256;

    // Blocks overlapping the rope region build the inv_freq table in smem
    // (double exp2 -> correctly-rounded fp32, same values as a double pow).
    if (blk0 < nA) {
        if (tid < DD/2)
            sfreq[tid] = (float)exp2(-(double)tid * LOG2_1E4_OVER_64);
        __syncthreads();
    }

    if (gid >= ntot) return;

    if (gid < nA) {
        // ---- RoPE keys ----
        int d4 = gid & 15;                 // lower-half float4 index (0..15)
        int h  = (gid >> 4) & (HH - 1);
        int p  = (gid >> 7) & (BUDGET - 1);
        int b  = gid >> 19;

        int ctx = *ctxp;
        int ql  = __ldg(&qlens[b]);

        const float4* row = resolve_row(cache, knew, b, p, 0, ctx, ql, maxkv, seq_len)
                            + h * VEC_PER_ROW;
        float4 x1 = __ldg(&row[d4]);
        float4 x2 = __ldg(&row[d4 + 16]);

        float fp = (float)p;
        int i0 = d4 * 4;
        float4 lo, hi;
        const float* a  = (const float*)&x1;
        const float* bb = (const float*)&x2;
        float* lf = (float*)&lo;
        float* hf = (float*)&hi;
        #pragma unroll
        for (int j = 0; j < 4; j++) {
            float s, c;
            __sincosf(fp * sfreq[i0 + j], &s, &c);   // MUFU fast path
            lf[j] = a[j] * c - bb[j] * s;
            hf[j] = a[j] * s + bb[j] * c;
        }

        float4* orow = out + out_row_base(b, p, 0, maxkv) + h * VEC_PER_ROW;
        orow[d4]      = lo;
        orow[d4 + 16] = hi;
    } else if (gid < nAV) {
        // ---- value gather, p < BUDGET (unchanged from R10) ----
        int j  = gid - nA;
        int d4 = (j & 15) * 2;             // pair of consecutive float4
        int h  = (j >> 4) & (HH - 1);
        int p  = (j >> 7) & (BUDGET - 1);
        int b  = j >> 19;

        int ctx = *ctxp;
        int ql  = __ldg(&qlens[b]);
        const float4* row = resolve_row(cache, vnew, b, p, 1, ctx, ql, maxkv, seq_len)
                            + h * VEC_PER_ROW;
        float4 v0 = __ldg(&row[d4]);
        float4 v1 = __ldg(&row[d4 + 1]);
        float4* orow = out + out_row_base(b, p, 1, maxkv) + h * VEC_PER_ROW;
        orow[d4]     = v0;
        orow[d4 + 1] = v1;
    } else {
        // ---- identity region: 4 warp-contiguous units, MLP 4 ----
        int j = gid - nAV;
        int b = j >> id_shift;
        int w = j & id_mask;               // per-batch thread index
        long long base = ((long long)b * (maxkv / PAGE) + (BUDGET / PAGE))
                         * F4_PER_PAGE;
        // group of 128 f4 per 32 threads; thread owns lanes {0,32,64,96}+lane
        long long idx = base + (long long)(w >> 5) * 128 + (w & 31);
        float4 v0 = __ldg(&cache[idx]);
        float4 v1 = __ldg(&cache[idx + 32]);
        float4 v2 = __ldg(&cache[idx + 64]);
        float4 v3 = __ldg(&cache[idx + 96]);
        out[idx]      = v0;
        out[idx + 32] = v1;
        out[idx + 64] = v2;
        out[idx + 96] = v3;
    }
}

extern "C" void kernel_launch(void* const* d_in, const int* in_sizes, int n_in,
                              void* d_out, int out_size) {
    const float4* cache = (const float4*)d_in[0];
    const float4* knew  = (const float4*)d_in[1];
    const float4* vnew  = (const float4*)d_in[2];
    const int*    qlens = (const int*)d_in[3];
    const int*    ctxp  = (const int*)d_in[5];   // context_len scalar (device)

    int bsz = in_sizes[3];
    int total_pos = in_sizes[0] / (2 * HH * DD);
    int maxkv = total_pos / bsz;                 // 8192
    int seq_len = in_sizes[1] / (bsz * HH * DD); // 2048

    // Region sizes (threads)
    int nA  = bsz * BUDGET * HH * (VEC_PER_ROW / 2);   // rope pairs
    int nV  = bsz * BUDGET * HH * (VEC_PER_ROW / 2);   // value 32B units
    int nAV = nA + nV;

    int id_pages = maxkv / PAGE - BUDGET / PAGE;                 // per batch
    long long id_thr = (long long)id_pages * F4_PER_PAGE / 4;    // threads/batch (pow2)
    int id_shift = 0;
    while ((1LL << id_shift) < id_thr) id_shift++;
    int id_mask = (int)(id_thr - 1);

    int ntot = nAV + (int)(id_thr * bsz);
    int blocks = (ntot + 255) / 256;

    skv_fused<<<blocks, 256>>>(cache, knew, vnew, qlens, ctxp,
                               (float4*)d_out, maxkv, seq_len,
                               nA, nAV, id_shift, id_mask, ntot);
}